// round 7
// baseline (speedup 1.0000x reference)
#include <cuda_runtime.h>
#include <cstdint>
#include <cstddef>

#define TPB 256

// ---------------- static device scratch (no allocations allowed) ----------------
__device__ int   g_win_idx[4096 * 64];
__device__ float g_win_val[4096 * 64];
__device__ float g_row_sq[4096];
__device__ int   g_defK[1] = {32};

// monotonic float->uint key: larger float => larger key
__device__ __forceinline__ unsigned fkey(float f) {
    unsigned u = __float_as_uint(f);
    return (u & 0x80000000u) ? ~u : (u | 0x80000000u);
}

// =================================================================================
// K1: raw = (x - b_dec) @ W_enc^T + b_enc   (NT sgemm, fp32 exact)
// A = x [N,D], B = W_enc [F,D], C = raw [N,F].  BM=BN=128, BK=16, 256 thr, 8x8/thr
// NOTE: C (the acts region of d_out) is only 4-byte aligned (odd float offset),
// so the epilogue MUST use scalar 32-bit stores. All float4 loads below target
// harness input buffers at multiple-of-4-float offsets (16B-aligned) — safe.
// =================================================================================
__global__ __launch_bounds__(256, 2)
void sgemm_enc(const float* __restrict__ A, const float* __restrict__ B,
               const float* __restrict__ b_enc, const float* __restrict__ b_dec,
               float* __restrict__ C, int N, int D, int F)
{
    __shared__ float As[16][128];
    __shared__ float Bs[16][128];

    const int tid = threadIdx.x;
    const int tx = tid & 15, ty = tid >> 4;
    const int m0 = blockIdx.y * 128, n0 = blockIdx.x * 128;

    const int lr = tid >> 2;          // 0..63
    const int lk = (tid & 3) * 4;     // 0,4,8,12

    const float* Ap0 = A + (size_t)(m0 + lr) * D + lk;
    const float* Ap1 = A + (size_t)(m0 + lr + 64) * D + lk;
    const float* Bp0 = B + (size_t)(n0 + lr) * D + lk;
    const float* Bp1 = B + (size_t)(n0 + lr + 64) * D + lk;

    float acc[8][8];
    #pragma unroll
    for (int i = 0; i < 8; ++i)
        #pragma unroll
        for (int j = 0; j < 8; ++j) acc[i][j] = 0.f;

    // prologue: stage 0 into registers
    float4 bd = *(const float4*)(b_dec + lk);
    float4 a0 = *(const float4*)(Ap0);
    float4 a1 = *(const float4*)(Ap1);
    float4 b0 = *(const float4*)(Bp0);
    float4 b1 = *(const float4*)(Bp1);
    a0.x -= bd.x; a0.y -= bd.y; a0.z -= bd.z; a0.w -= bd.w;
    a1.x -= bd.x; a1.y -= bd.y; a1.z -= bd.z; a1.w -= bd.w;

    int kk = 0;
    for (;;) {
        __syncthreads();
        // store stage (transposed to k-major)
        As[lk + 0][lr] = a0.x; As[lk + 1][lr] = a0.y; As[lk + 2][lr] = a0.z; As[lk + 3][lr] = a0.w;
        As[lk + 0][lr + 64] = a1.x; As[lk + 1][lr + 64] = a1.y; As[lk + 2][lr + 64] = a1.z; As[lk + 3][lr + 64] = a1.w;
        Bs[lk + 0][lr] = b0.x; Bs[lk + 1][lr] = b0.y; Bs[lk + 2][lr] = b0.z; Bs[lk + 3][lr] = b0.w;
        Bs[lk + 0][lr + 64] = b1.x; Bs[lk + 1][lr + 64] = b1.y; Bs[lk + 2][lr + 64] = b1.z; Bs[lk + 3][lr + 64] = b1.w;
        __syncthreads();

        kk += 16;
        const bool more = (kk < D);
        if (more) {   // prefetch next stage while computing this one
            bd = *(const float4*)(b_dec + kk + lk);
            a0 = *(const float4*)(Ap0 + kk);
            a1 = *(const float4*)(Ap1 + kk);
            b0 = *(const float4*)(Bp0 + kk);
            b1 = *(const float4*)(Bp1 + kk);
            a0.x -= bd.x; a0.y -= bd.y; a0.z -= bd.z; a0.w -= bd.w;
            a1.x -= bd.x; a1.y -= bd.y; a1.z -= bd.z; a1.w -= bd.w;
        }

        #pragma unroll
        for (int k = 0; k < 16; ++k) {
            float4 al = *(const float4*)&As[k][ty * 8];
            float4 ah = *(const float4*)&As[k][ty * 8 + 4];
            float4 bl = *(const float4*)&Bs[k][tx * 8];
            float4 bh = *(const float4*)&Bs[k][tx * 8 + 4];
            float ra[8] = {al.x, al.y, al.z, al.w, ah.x, ah.y, ah.z, ah.w};
            float rb[8] = {bl.x, bl.y, bl.z, bl.w, bh.x, bh.y, bh.z, bh.w};
            #pragma unroll
            for (int i = 0; i < 8; ++i)
                #pragma unroll
                for (int j = 0; j < 8; ++j)
                    acc[i][j] = fmaf(ra[i], rb[j], acc[i][j]);
        }
        if (!more) break;
    }

    // epilogue: + b_enc, store — SCALAR stores (C is only 4B-aligned)
    float be[8];
    #pragma unroll
    for (int j = 0; j < 8; ++j) be[j] = b_enc[n0 + tx * 8 + j];
    #pragma unroll
    for (int i = 0; i < 8; ++i) {
        float* crow = C + (size_t)(m0 + ty * 8 + i) * F + n0 + tx * 8;
        #pragma unroll
        for (int j = 0; j < 8; ++j)
            crow[j] = acc[i][j] + be[j];
    }
}

// =================================================================================
// K2: per-row exact top-K selection (radix select on sortable keys),
//     ties broken by lowest index (matches jax.lax.top_k). In-place mask of acts.
//     Also emits compact winner (idx,val) lists for the decoder.
// =================================================================================
__global__ void topk_kernel(float* __restrict__ acts, const int* __restrict__ pK, int F)
{
    extern __shared__ unsigned char smem_raw[];
    float*    vals = (float*)smem_raw;                 // F floats
    unsigned* hist = (unsigned*)(vals + F);            // 256
    unsigned* bits = hist + 256;                       // F/32 words
    int*      misc = (int*)(bits + (F >> 5));          // [0]=digit [1]=gt [2..] warp stuff

    const int row = blockIdx.x;
    const int tid = threadIdx.x;
    int K = *pK; if (K > 64) K = 64; if (K < 1) K = 1;
    const size_t rowoff = (size_t)row * F;

    for (int i = tid; i < F; i += TPB) vals[i] = acts[rowoff + i];
    __syncthreads();

    // ---- 4-level radix select (descending) ----
    unsigned prefix = 0;
    int need = K;
    for (int lvl = 0; lvl < 4; ++lvl) {
        const int shift = 24 - lvl * 8;
        hist[tid] = 0;
        __syncthreads();
        for (int i = tid; i < F; i += TPB) {
            unsigned u = fkey(vals[i]);
            bool match = (lvl == 0) || ((u >> (shift + 8)) == prefix);
            if (match) atomicAdd(&hist[(u >> shift) & 255u], 1u);
        }
        __syncthreads();
        // inclusive suffix scan over 256 bins
        for (int off = 1; off < 256; off <<= 1) {
            unsigned v = hist[tid];
            if (tid + off < 256) v += hist[tid + off];
            __syncthreads();
            hist[tid] = v;
            __syncthreads();
        }
        unsigned ge = hist[tid];
        unsigned gt = (tid == 255) ? 0u : hist[tid + 1];
        if ((int)ge >= need && (int)gt < need) { misc[0] = tid; misc[1] = (int)gt; }
        __syncthreads();
        need -= misc[1];
        prefix = (prefix << 8) | (unsigned)misc[0];
        __syncthreads();
    }
    const unsigned T = prefix;   // exact key of K-th largest
    const int r = need;          // how many elements equal to T to take (lowest index first)

    // ---- ordered enumeration: 8 warps, contiguous segments ----
    const int warp = tid >> 5, lane = tid & 31;
    const unsigned lml = (1u << lane) - 1u;
    const int chunks = F >> 5;
    const int cpw = chunks >> 3;
    const int c0 = warp * cpw;

    int gt_cnt = 0, eq_cnt = 0;
    for (int c = 0; c < cpw; ++c) {
        unsigned u = fkey(vals[((c0 + c) << 5) + lane]);
        gt_cnt += __popc(__ballot_sync(0xffffffffu, u > T));
        eq_cnt += __popc(__ballot_sync(0xffffffffu, u == T));
    }
    int* wgt = misc + 2; int* weq = wgt + 8; int* wgto = weq + 8; int* weqo = wgto + 8;
    if (lane == 0) { wgt[warp] = gt_cnt; weq[warp] = eq_cnt; }
    __syncthreads();
    if (tid == 0) {
        int ag = 0, ae = 0;
        for (int w = 0; w < 8; ++w) { wgto[w] = ag; ag += wgt[w]; weqo[w] = ae; ae += weq[w]; }
        misc[34] = ag;  // total count of strictly-greater
    }
    __syncthreads();
    int gpos = wgto[warp], epos = weqo[warp];
    const int totgt = misc[34];

    for (int c = 0; c < cpw; ++c) {
        const int widx = c0 + c;
        const int idx = (widx << 5) + lane;
        const float v = vals[idx];
        const unsigned u = fkey(v);
        unsigned mg = __ballot_sync(0xffffffffu, u > T);
        unsigned me = __ballot_sync(0xffffffffu, u == T);
        int eqr = epos + __popc(me & lml);
        bool seq = (u == T) && (eqr < r);
        unsigned ms = __ballot_sync(0xffffffffu, seq);
        if (lane == 0) bits[widx] = mg | ms;
        if (u > T) {
            int p = gpos + __popc(mg & lml);
            g_win_idx[(row << 6) + p] = idx;
            g_win_val[(row << 6) + p] = v;
        } else if (seq) {
            int p = totgt + eqr;
            g_win_idx[(row << 6) + p] = idx;
            g_win_val[(row << 6) + p] = v;
        }
        gpos += __popc(mg); epos += __popc(me);
    }
    __syncthreads();

    // ---- masked write-back (scalar stores: acts is 4B-aligned only) ----
    for (int i = tid; i < F; i += TPB) {
        unsigned w = bits[i >> 5];
        acts[rowoff + i] = ((w >> (i & 31)) & 1u) ? vals[i] : 0.0f;
    }
}

// =================================================================================
// K3: sparse decoder: recon[n,:] = b_dec + sum_j val_j * W_dec[idx_j,:]
//     + per-row squared error
// =================================================================================
__global__ void decoder_kernel(const float* __restrict__ x, const float* __restrict__ Wd,
                               const float* __restrict__ b_dec, const int* __restrict__ pK,
                               float* __restrict__ recon, int D)
{
    __shared__ int   wi[64];
    __shared__ float wv[64];
    __shared__ float red[TPB];
    const int row = blockIdx.x, tid = threadIdx.x;
    int K = *pK; if (K > 64) K = 64; if (K < 1) K = 1;
    if (tid < K) { wi[tid] = g_win_idx[(row << 6) + tid]; wv[tid] = g_win_val[(row << 6) + tid]; }
    __syncthreads();

    float sq = 0.f;
    for (int d = tid; d < D; d += TPB) {
        float acc = b_dec[d];
        #pragma unroll 4
        for (int j = 0; j < K; ++j)
            acc = fmaf(wv[j], Wd[(size_t)wi[j] * D + d], acc);
        recon[(size_t)row * D + d] = acc;
        float df = acc - x[(size_t)row * D + d];
        sq = fmaf(df, df, sq);
    }
    red[tid] = sq;
    __syncthreads();
    for (int s = TPB / 2; s > 0; s >>= 1) {
        if (tid < s) red[tid] += red[tid + s];
        __syncthreads();
    }
    if (tid == 0) g_row_sq[row] = red[0];
}

// =================================================================================
// K4: loss = mean(row_sq)
// =================================================================================
__global__ void loss_kernel(float* __restrict__ out, int N)
{
    __shared__ float red[TPB];
    const int tid = threadIdx.x;
    float s = 0.f;
    for (int i = tid; i < N; i += TPB) s += g_row_sq[i];
    red[tid] = s;
    __syncthreads();
    for (int o = TPB / 2; o > 0; o >>= 1) {
        if (tid < o) red[tid] += red[tid + o];
        __syncthreads();
    }
    if (tid == 0) out[0] = red[0] / (float)N;
}

// =================================================================================
// launch: out = [loss(1), recon(N*D), acts(N*F)]
// =================================================================================
extern "C" void kernel_launch(void* const* d_in, const int* in_sizes, int n_in,
                              void* d_out, int out_size)
{
    const float* x   = (const float*)d_in[0];
    const float* W_e = (const float*)d_in[1];
    const float* W_d = (const float*)d_in[2];
    const float* b_e = (const float*)d_in[3];
    const float* b_d = (const float*)d_in[4];

    const int* pK;
    if (n_in >= 6) {
        pK = (const int*)d_in[5];
    } else {
        void* p = nullptr;
        cudaGetSymbolAddress(&p, g_defK);
        pK = (const int*)p;
    }

    const int D = in_sizes[4];            // b_dec length
    const int F = in_sizes[3];            // b_enc length
    const int N = in_sizes[0] / D;        // x rows

    float* out   = (float*)d_out;
    float* recon = out + 1;
    float* acts  = out + 1 + (size_t)N * D;

    // K1: encoder GEMM -> raw (stored in acts region)
    dim3 grid(F / 128, N / 128);
    sgemm_enc<<<grid, TPB>>>(x, W_e, b_e, b_d, acts, N, D, F);

    // K2: per-row top-K mask (in place)
    size_t smem2 = (size_t)F * 4 + 256 * 4 + (size_t)(F >> 5) * 4 + 64 * 4;
    cudaFuncSetAttribute(topk_kernel, cudaFuncAttributeMaxDynamicSharedMemorySize, (int)smem2);
    topk_kernel<<<N, TPB, smem2>>>(acts, pK, F);

    // K3: sparse decoder + row squared error
    decoder_kernel<<<N, TPB>>>(x, W_d, b_d, pK, recon, D);

    // K4: loss
    loss_kernel<<<1, TPB>>>(out, N);
}

// round 8
// speedup vs baseline: 3.2854x; 3.2854x over previous
#include <cuda_runtime.h>
#include <cuda_bf16.h>
#include <cstdint>
#include <cstddef>

#define TPB 256

// fixed problem shape upper bounds (N=4096, D=512, F=16384)
#define MAXN 4096
#define MAXD 512
#define MAXF 16384
#define NCAND_MAX 128

// ---------------- static device scratch (no allocations allowed) ----------------
__device__ __nv_bfloat16 g_Abf[(size_t)MAXN * MAXD];          // x - b_dec, bf16
__device__ __nv_bfloat16 g_Wbf[(size_t)MAXF * MAXD];          // W_enc, bf16
__device__ __nv_bfloat16 g_screen[(size_t)MAXN * MAXF];       // screened scores, bf16
__device__ int   g_cand[(size_t)MAXN * NCAND_MAX];
__device__ int   g_win_idx[MAXN * 64];
__device__ float g_win_val[MAXN * 64];
__device__ float g_row_sq[MAXN];
__device__ int   g_defK[1] = {32};

// monotonic float->uint key: larger float => larger key
__device__ __forceinline__ unsigned fkey(float f) {
    unsigned u = __float_as_uint(f);
    return (u & 0x80000000u) ? ~u : (u | 0x80000000u);
}
// same for bf16 bit pattern (16-bit key)
__device__ __forceinline__ unsigned key16(unsigned u) {
    return (u & 0x8000u) ? ((~u) & 0xFFFFu) : (u | 0x8000u);
}
__device__ __forceinline__ int clampK(int K) {
    if (K > 64) K = 64; if (K < 1) K = 1; return K;
}
__device__ __forceinline__ int ncand_of(int K) {
    int nc = 2 * K; if (nc < 64) nc = 64; if (nc > NCAND_MAX) nc = NCAND_MAX; return nc;
}

// ---------------- PTX helpers ----------------
__device__ __forceinline__ void ldsm4(uint32_t& r0, uint32_t& r1, uint32_t& r2, uint32_t& r3,
                                      const void* p) {
    uint32_t a = (uint32_t)__cvta_generic_to_shared(p);
    asm volatile("ldmatrix.sync.aligned.m8n8.x4.shared.b16 {%0,%1,%2,%3},[%4];"
                 : "=r"(r0), "=r"(r1), "=r"(r2), "=r"(r3) : "r"(a));
}
__device__ __forceinline__ void mma16816(float c[4],
                                         uint32_t a0, uint32_t a1, uint32_t a2, uint32_t a3,
                                         uint32_t b0, uint32_t b1) {
    asm volatile("mma.sync.aligned.m16n8k16.row.col.f32.bf16.bf16.f32 "
                 "{%0,%1,%2,%3},{%4,%5,%6,%7},{%8,%9},{%0,%1,%2,%3};"
                 : "+f"(c[0]), "+f"(c[1]), "+f"(c[2]), "+f"(c[3])
                 : "r"(a0), "r"(a1), "r"(a2), "r"(a3), "r"(b0), "r"(b1));
}

// =================================================================================
// K0a: W_enc -> bf16
// =================================================================================
__global__ void prep_w(const float* __restrict__ W, __nv_bfloat16* __restrict__ Wb, size_t n)
{
    size_t i = (size_t)blockIdx.x * blockDim.x + threadIdx.x;
    size_t stride = (size_t)gridDim.x * blockDim.x;
    for (; i < n; i += stride) Wb[i] = __float2bfloat16(W[i]);
}
// K0b: (x - b_dec) -> bf16
__global__ void prep_x(const float* __restrict__ x, const float* __restrict__ b_dec,
                       __nv_bfloat16* __restrict__ Ab, int N, int D)
{
    size_t n = (size_t)N * D;
    size_t i = (size_t)blockIdx.x * blockDim.x + threadIdx.x;
    size_t stride = (size_t)gridDim.x * blockDim.x;
    for (; i < n; i += stride) {
        int d = (int)(i % D);
        Ab[i] = __float2bfloat16(x[i] - b_dec[d]);
    }
}

// =================================================================================
// K1: screening GEMM (bf16 tensor cores, fp32 accum):
//     screen = (x-b_dec)_bf16 @ W_enc_bf16^T + b_enc, stored bf16 [N,F]
// BM=BN=128, BK=32, 256 thr = 8 warps (2m x 4n), warp tile 64x32, mma m16n8k16
// smem rows padded to 40 bf16 (80B) -> conflict-free ldmatrix
// =================================================================================
__global__ __launch_bounds__(256, 1)
void gemm_screen(const __nv_bfloat16* __restrict__ A, const __nv_bfloat16* __restrict__ Bw,
                 const float* __restrict__ b_enc, __nv_bfloat16* __restrict__ Cs,
                 int N, int D, int F)
{
    __shared__ __align__(16) __nv_bfloat16 As[128 * 40];
    __shared__ __align__(16) __nv_bfloat16 Bs[128 * 40];
    __shared__ float benc_s[128];

    const int tid = threadIdx.x;
    const int m0 = blockIdx.y * 128, n0 = blockIdx.x * 128;
    if (tid < 128) benc_s[tid] = b_enc[n0 + tid];

    const int warp = tid >> 5, lane = tid & 31;
    const int wm = warp & 1, wn = warp >> 1;

    const int lrow = tid >> 2;           // 0..63
    const int lq   = (tid & 3) * 8;      // bf16 col: 0,8,16,24

    const __nv_bfloat16* Ag0 = A  + (size_t)(m0 + lrow) * D + lq;
    const __nv_bfloat16* Ag1 = A  + (size_t)(m0 + lrow + 64) * D + lq;
    const __nv_bfloat16* Bg0 = Bw + (size_t)(n0 + lrow) * D + lq;
    const __nv_bfloat16* Bg1 = Bw + (size_t)(n0 + lrow + 64) * D + lq;

    float acc[4][4][4];
    #pragma unroll
    for (int mi = 0; mi < 4; ++mi)
        #pragma unroll
        for (int ni = 0; ni < 4; ++ni)
            #pragma unroll
            for (int t = 0; t < 4; ++t) acc[mi][ni][t] = 0.f;

    // prologue loads
    uint4 ra0 = *(const uint4*)Ag0;
    uint4 ra1 = *(const uint4*)Ag1;
    uint4 rb0 = *(const uint4*)Bg0;
    uint4 rb1 = *(const uint4*)Bg1;

    const int arow_base = wm * 64 + (lane & 7) + ((lane & 8) ? 8 : 0);
    const int acol_base = (lane & 16) ? 8 : 0;
    const int brow_base = wn * 32 + (lane & 7) + ((lane & 16) ? 8 : 0);
    const int bcol_base = (lane & 8) ? 8 : 0;

    int kk = 0;
    for (;;) {
        __syncthreads();
        *(uint4*)(As + lrow * 40 + lq)        = ra0;
        *(uint4*)(As + (lrow + 64) * 40 + lq) = ra1;
        *(uint4*)(Bs + lrow * 40 + lq)        = rb0;
        *(uint4*)(Bs + (lrow + 64) * 40 + lq) = rb1;
        __syncthreads();

        kk += 32;
        const bool more = (kk < D);
        if (more) {
            ra0 = *(const uint4*)(Ag0 + kk);
            ra1 = *(const uint4*)(Ag1 + kk);
            rb0 = *(const uint4*)(Bg0 + kk);
            rb1 = *(const uint4*)(Bg1 + kk);
        }

        #pragma unroll
        for (int ks = 0; ks < 2; ++ks) {
            uint32_t af[4][4];
            const int acol = ks * 16 + acol_base;
            #pragma unroll
            for (int mi = 0; mi < 4; ++mi)
                ldsm4(af[mi][0], af[mi][1], af[mi][2], af[mi][3],
                      As + (arow_base + mi * 16) * 40 + acol);

            uint32_t bfr[4][2];
            const int bcol = ks * 16 + bcol_base;
            #pragma unroll
            for (int nj = 0; nj < 2; ++nj) {
                uint32_t r0, r1, r2, r3;
                ldsm4(r0, r1, r2, r3, Bs + (brow_base + nj * 16) * 40 + bcol);
                bfr[nj * 2][0] = r0; bfr[nj * 2][1] = r1;
                bfr[nj * 2 + 1][0] = r2; bfr[nj * 2 + 1][1] = r3;
            }

            #pragma unroll
            for (int mi = 0; mi < 4; ++mi)
                #pragma unroll
                for (int ni = 0; ni < 4; ++ni)
                    mma16816(acc[mi][ni], af[mi][0], af[mi][1], af[mi][2], af[mi][3],
                             bfr[ni][0], bfr[ni][1]);
        }
        if (!more) break;
    }

    // epilogue: + b_enc, convert bf16, store (4B stores, screen buffer aligned)
    #pragma unroll
    for (int mi = 0; mi < 4; ++mi) {
        const int gm = m0 + wm * 64 + mi * 16 + (lane >> 2);
        #pragma unroll
        for (int ni = 0; ni < 4; ++ni) {
            const int ln = wn * 32 + ni * 8 + (lane & 3) * 2;
            const float be0 = benc_s[ln], be1 = benc_s[ln + 1];
            __nv_bfloat162 h0 = __floats2bfloat162_rn(acc[mi][ni][0] + be0, acc[mi][ni][1] + be1);
            __nv_bfloat162 h1 = __floats2bfloat162_rn(acc[mi][ni][2] + be0, acc[mi][ni][3] + be1);
            *(__nv_bfloat162*)(Cs + (size_t)gm * F + n0 + ln)       = h0;
            *(__nv_bfloat162*)(Cs + (size_t)(gm + 8) * F + n0 + ln) = h1;
        }
    }
}

// =================================================================================
// K2: per-row candidate top-ncand on bf16 screened scores (2-level radix select,
//     ties -> lowest index). Writes candidate indices. Also zeroes the acts row.
// =================================================================================
__global__ void cand_topk(const __nv_bfloat16* __restrict__ S, const int* __restrict__ pK,
                          float* __restrict__ acts, int F)
{
    extern __shared__ unsigned char smem_raw[];
    unsigned short* keys = (unsigned short*)smem_raw;        // F keys
    unsigned* hist = (unsigned*)(keys + F);                  // 256
    int* misc = (int*)(hist + 256);                          // [0]=digit [1]=gt [2..] warp

    const int row = blockIdx.x;
    const int tid = threadIdx.x;
    const int ncand = ncand_of(clampK(*pK));
    const size_t rowoff = (size_t)row * F;

    // load + transform to 16-bit sortable keys
    const uint32_t* rp = (const uint32_t*)(S + rowoff);
    for (int i = tid; i < (F >> 1); i += TPB) {
        uint32_t v = rp[i];
        keys[2 * i]     = (unsigned short)key16(v & 0xFFFFu);
        keys[2 * i + 1] = (unsigned short)key16(v >> 16);
    }
    __syncthreads();

    // ---- 2-level radix select (descending) ----
    unsigned prefix = 0;
    int need = ncand;
    for (int lvl = 0; lvl < 2; ++lvl) {
        const int shift = (1 - lvl) * 8;
        hist[tid] = 0;
        __syncthreads();
        for (int i = tid; i < F; i += TPB) {
            unsigned u = keys[i];
            bool match = (lvl == 0) || ((u >> 8) == prefix);
            if (match) atomicAdd(&hist[(u >> shift) & 255u], 1u);
        }
        __syncthreads();
        for (int off = 1; off < 256; off <<= 1) {
            unsigned v = hist[tid];
            if (tid + off < 256) v += hist[tid + off];
            __syncthreads();
            hist[tid] = v;
            __syncthreads();
        }
        unsigned ge = hist[tid];
        unsigned gt = (tid == 255) ? 0u : hist[tid + 1];
        if ((int)ge >= need && (int)gt < need) { misc[0] = tid; misc[1] = (int)gt; }
        __syncthreads();
        need -= misc[1];
        prefix = (prefix << 8) | (unsigned)misc[0];
        __syncthreads();
    }
    const unsigned T = prefix;   // exact 16-bit key of ncand-th largest
    const int r = need;          // ties at T to take (lowest index first)

    // ---- ordered enumeration: 8 warps, contiguous segments ----
    const int warp = tid >> 5, lane = tid & 31;
    const unsigned lml = (1u << lane) - 1u;
    const int cpw = (F >> 5) >> 3;
    const int c0 = warp * cpw;

    int gt_cnt = 0, eq_cnt = 0;
    for (int c = 0; c < cpw; ++c) {
        unsigned u = keys[((c0 + c) << 5) + lane];
        gt_cnt += __popc(__ballot_sync(0xffffffffu, u > T));
        eq_cnt += __popc(__ballot_sync(0xffffffffu, u == T));
    }
    int* wgt = misc + 2; int* weq = wgt + 8; int* wgto = weq + 8; int* weqo = wgto + 8;
    if (lane == 0) { wgt[warp] = gt_cnt; weq[warp] = eq_cnt; }
    __syncthreads();
    if (tid == 0) {
        int ag = 0, ae = 0;
        for (int w = 0; w < 8; ++w) { wgto[w] = ag; ag += wgt[w]; weqo[w] = ae; ae += weq[w]; }
        misc[34] = ag;
    }
    __syncthreads();
    int gpos = wgto[warp], epos = weqo[warp];
    const int totgt = misc[34];

    for (int c = 0; c < cpw; ++c) {
        const int idx = ((c0 + c) << 5) + lane;
        const unsigned u = keys[idx];
        unsigned mg = __ballot_sync(0xffffffffu, u > T);
        unsigned me = __ballot_sync(0xffffffffu, u == T);
        int eqr = epos + __popc(me & lml);
        if (u > T) {
            int p = gpos + __popc(mg & lml);
            g_cand[(size_t)row * NCAND_MAX + p] = idx;
        } else if (u == T && eqr < r) {
            g_cand[(size_t)row * NCAND_MAX + totgt + eqr] = idx;
        }
        gpos += __popc(mg); epos += __popc(me);
    }

    // zero this row of acts (rescore scatters winners afterwards)
    for (int i = tid; i < F; i += TPB) acts[rowoff + i] = 0.0f;
}

// =================================================================================
// K3: exact fp32 rescore of candidates + exact top-K ranking (ties: lowest index)
//     scatters winners into acts, records (idx,val) for decoder.
// =================================================================================
__global__ __launch_bounds__(256)
void rescore(const float* __restrict__ x, const float* __restrict__ W,
             const float* __restrict__ b_enc, const float* __restrict__ b_dec,
             const int* __restrict__ pK, float* __restrict__ acts, int D, int F)
{
    __shared__ float xc[MAXD];
    __shared__ float sc[NCAND_MAX];
    __shared__ int   ci[NCAND_MAX];

    const int row = blockIdx.x;
    const int tid = threadIdx.x;
    const int K = clampK(*pK);
    const int ncand = ncand_of(K);

    for (int i = tid; i < D; i += TPB) xc[i] = x[(size_t)row * D + i] - b_dec[i];
    __syncthreads();

    const int warp = tid >> 5, lane = tid & 31;
    for (int c = warp; c < ncand; c += 8) {
        const int f = g_cand[(size_t)row * NCAND_MAX + c];
        const float* wrow = W + (size_t)f * D;
        float s = 0.f;
        for (int j = lane; j < D; j += 32) s = fmaf(xc[j], wrow[j], s);
        #pragma unroll
        for (int off = 16; off > 0; off >>= 1)
            s += __shfl_down_sync(0xffffffffu, s, off);
        if (lane == 0) { sc[c] = s + b_enc[f]; ci[c] = f; }
    }
    __syncthreads();

    // exact ranking among candidates: rank = #{j beats i}; beats = (>) or (== && lower idx)
    for (int c = tid; c < ncand; c += TPB) {
        const unsigned ki = fkey(sc[c]);
        const int idi = ci[c];
        int rank = 0;
        for (int j = 0; j < ncand; ++j) {
            unsigned kj = fkey(sc[j]);
            rank += (kj > ki) || (kj == ki && ci[j] < idi);
        }
        if (rank < K) {
            g_win_idx[(row << 6) + rank] = idi;
            g_win_val[(row << 6) + rank] = sc[c];
            acts[(size_t)row * F + idi] = sc[c];
        }
    }
}

// =================================================================================
// K4: sparse decoder + per-row squared error
// =================================================================================
__global__ void decoder_kernel(const float* __restrict__ x, const float* __restrict__ Wd,
                               const float* __restrict__ b_dec, const int* __restrict__ pK,
                               float* __restrict__ recon, int D)
{
    __shared__ int   wi[64];
    __shared__ float wv[64];
    __shared__ float red[TPB];
    const int row = blockIdx.x, tid = threadIdx.x;
    const int K = clampK(*pK);
    if (tid < K) { wi[tid] = g_win_idx[(row << 6) + tid]; wv[tid] = g_win_val[(row << 6) + tid]; }
    __syncthreads();

    float sq = 0.f;
    for (int d = tid; d < D; d += TPB) {
        float acc = b_dec[d];
        #pragma unroll 4
        for (int j = 0; j < K; ++j)
            acc = fmaf(wv[j], Wd[(size_t)wi[j] * D + d], acc);
        recon[(size_t)row * D + d] = acc;
        float df = acc - x[(size_t)row * D + d];
        sq = fmaf(df, df, sq);
    }
    red[tid] = sq;
    __syncthreads();
    for (int s = TPB / 2; s > 0; s >>= 1) {
        if (tid < s) red[tid] += red[tid + s];
        __syncthreads();
    }
    if (tid == 0) g_row_sq[row] = red[0];
}

// =================================================================================
// K5: loss = mean(row_sq)
// =================================================================================
__global__ void loss_kernel(float* __restrict__ out, int N)
{
    __shared__ float red[TPB];
    const int tid = threadIdx.x;
    float s = 0.f;
    for (int i = tid; i < N; i += TPB) s += g_row_sq[i];
    red[tid] = s;
    __syncthreads();
    for (int o = TPB / 2; o > 0; o >>= 1) {
        if (tid < o) red[tid] += red[tid + o];
        __syncthreads();
    }
    if (tid == 0) out[0] = red[0] / (float)N;
}

// =================================================================================
// launch: out = [loss(1), recon(N*D), acts(N*F)]
// =================================================================================
extern "C" void kernel_launch(void* const* d_in, const int* in_sizes, int n_in,
                              void* d_out, int out_size)
{
    const float* x   = (const float*)d_in[0];
    const float* W_e = (const float*)d_in[1];
    const float* W_d = (const float*)d_in[2];
    const float* b_e = (const float*)d_in[3];
    const float* b_d = (const float*)d_in[4];

    const int* pK;
    if (n_in >= 6) {
        pK = (const int*)d_in[5];
    } else {
        void* p = nullptr;
        cudaGetSymbolAddress(&p, g_defK);
        pK = (const int*)p;
    }

    const int D = in_sizes[4];
    const int F = in_sizes[3];
    const int N = in_sizes[0] / D;

    float* out   = (float*)d_out;
    float* recon = out + 1;
    float* acts  = out + 1 + (size_t)N * D;

    __nv_bfloat16 *Abf, *Wbf, *Scr;
    { void* p; cudaGetSymbolAddress(&p, g_Abf);    Abf = (__nv_bfloat16*)p; }
    { void* p; cudaGetSymbolAddress(&p, g_Wbf);    Wbf = (__nv_bfloat16*)p; }
    { void* p; cudaGetSymbolAddress(&p, g_screen); Scr = (__nv_bfloat16*)p; }

    // K0: bf16 conversions
    prep_x<<<(N * D + 1023) / 1024, 256>>>(x, b_d, Abf, N, D);
    prep_w<<<((size_t)F * D + 1023) / 1024, 256>>>(W_e, Wbf, (size_t)F * D);

    // K1: bf16 tensor-core screening GEMM
    dim3 grid(F / 128, N / 128);
    gemm_screen<<<grid, TPB>>>(Abf, Wbf, b_e, Scr, N, D, F);

    // K2: candidate selection (+ zero acts rows)
    size_t smem2 = (size_t)F * 2 + 256 * 4 + 64 * 4;
    cand_topk<<<N, TPB, smem2>>>(Scr, pK, acts, F);

    // K3: exact rescore + exact top-K + scatter
    rescore<<<N, TPB>>>(x, W_e, b_e, b_d, pK, acts, D, F);

    // K4: sparse decoder + row squared error
    decoder_kernel<<<N, TPB>>>(x, W_d, b_d, pK, recon, D);

    // K5: loss
    loss_kernel<<<1, TPB>>>(out, N);
}

// round 10
// speedup vs baseline: 3.6003x; 1.0959x over previous
#include <cuda_runtime.h>
#include <cuda_bf16.h>
#include <cstdint>
#include <cstddef>

#define TPB 256

// fixed problem shape upper bounds (N=4096, D=512, F=16384)
#define MAXN 4096
#define MAXD 512
#define MAXF 16384
#define NCAND_MAX 128

// ---------------- static device scratch (no allocations allowed) ----------------
__device__ __nv_bfloat16 g_Abf[(size_t)MAXN * MAXD];          // x - b_dec, bf16
__device__ __nv_bfloat16 g_Wbf[(size_t)MAXF * MAXD];          // W_enc, bf16
__device__ __nv_bfloat16 g_screen[(size_t)MAXN * MAXF];       // screened scores, bf16
__device__ int   g_cand[(size_t)MAXN * NCAND_MAX];
__device__ int   g_candn[MAXN];
__device__ int   g_win_idx[MAXN * 64];
__device__ float g_win_val[MAXN * 64];
__device__ float g_row_sq[MAXN];
__device__ int   g_defK[1] = {32};

// monotonic float->uint key: larger float => larger key
__device__ __forceinline__ unsigned fkey(float f) {
    unsigned u = __float_as_uint(f);
    return (u & 0x80000000u) ? ~u : (u | 0x80000000u);
}
__device__ __forceinline__ int clampK(int K) {
    if (K > 64) K = 64; if (K < 1) K = 1; return K;
}
__device__ __forceinline__ int ncand_of(int K) {
    int nc = 2 * K; if (nc < 64) nc = 64; if (nc > NCAND_MAX) nc = NCAND_MAX; return nc;
}

// ---------------- PTX helpers (portable: sm_80+ features only; NO tcgen05 — the
// harness builds via compute_103 virtual target which lacks arch-specific insts) ----
__device__ __forceinline__ void ldsm4(uint32_t& r0, uint32_t& r1, uint32_t& r2, uint32_t& r3,
                                      const void* p) {
    uint32_t a = (uint32_t)__cvta_generic_to_shared(p);
    asm volatile("ldmatrix.sync.aligned.m8n8.x4.shared.b16 {%0,%1,%2,%3},[%4];"
                 : "=r"(r0), "=r"(r1), "=r"(r2), "=r"(r3) : "r"(a));
}
__device__ __forceinline__ void mma16816(float c[4],
                                         uint32_t a0, uint32_t a1, uint32_t a2, uint32_t a3,
                                         uint32_t b0, uint32_t b1) {
    asm volatile("mma.sync.aligned.m16n8k16.row.col.f32.bf16.bf16.f32 "
                 "{%0,%1,%2,%3},{%4,%5,%6,%7},{%8,%9},{%0,%1,%2,%3};"
                 : "+f"(c[0]), "+f"(c[1]), "+f"(c[2]), "+f"(c[3])
                 : "r"(a0), "r"(a1), "r"(a2), "r"(a3), "r"(b0), "r"(b1));
}
__device__ __forceinline__ void cp16(void* smem_dst, const void* gmem_src) {
    uint32_t a = (uint32_t)__cvta_generic_to_shared(smem_dst);
    asm volatile("cp.async.cg.shared.global [%0], [%1], 16;" :: "r"(a), "l"(gmem_src));
}
#define CP_COMMIT() asm volatile("cp.async.commit_group;" ::: "memory")
#define CP_WAIT(n)  asm volatile("cp.async.wait_group %0;" :: "n"(n) : "memory")

// =================================================================================
// K0a: W_enc -> bf16 (vectorized)
// =================================================================================
__global__ void prep_w(const float* __restrict__ W, __nv_bfloat16* __restrict__ Wb, size_t n4)
{
    size_t i = (size_t)blockIdx.x * blockDim.x + threadIdx.x;
    size_t stride = (size_t)gridDim.x * blockDim.x;
    for (; i < n4; i += stride) {
        float4 v = ((const float4*)W)[i];
        __nv_bfloat162 lo = __floats2bfloat162_rn(v.x, v.y);
        __nv_bfloat162 hi = __floats2bfloat162_rn(v.z, v.w);
        ((uint2*)Wb)[i] = make_uint2(*(uint32_t*)&lo, *(uint32_t*)&hi);
    }
}
// K0b: (x - b_dec) -> bf16
__global__ void prep_x(const float* __restrict__ x, const float* __restrict__ b_dec,
                       __nv_bfloat16* __restrict__ Ab, int N, int D)
{
    size_t n4 = ((size_t)N * D) >> 2;
    int D4 = D >> 2;
    size_t i = (size_t)blockIdx.x * blockDim.x + threadIdx.x;
    size_t stride = (size_t)gridDim.x * blockDim.x;
    for (; i < n4; i += stride) {
        float4 v = ((const float4*)x)[i];
        float4 b = ((const float4*)b_dec)[i % D4];
        __nv_bfloat162 lo = __floats2bfloat162_rn(v.x - b.x, v.y - b.y);
        __nv_bfloat162 hi = __floats2bfloat162_rn(v.z - b.z, v.w - b.w);
        ((uint2*)Ab)[i] = make_uint2(*(uint32_t*)&lo, *(uint32_t*)&hi);
    }
}

// =================================================================================
// K1: screening GEMM (bf16 mma.sync, fp32 accum), cp.async 2-stage pipeline:
//     screen = (x-b_dec)_bf16 @ W_enc_bf16^T + b_enc, stored bf16 [N,F]
// BM=BN=128, BK=32, 256 thr = 8 warps (2m x 4n), warp tile 64x32, mma m16n8k16
// smem rows padded to 40 bf16 (80B, 16B-aligned stride) -> conflict-free ldmatrix
// =================================================================================
__global__ __launch_bounds__(256, 1)
void gemm_screen(const __nv_bfloat16* __restrict__ A, const __nv_bfloat16* __restrict__ Bw,
                 const float* __restrict__ b_enc, __nv_bfloat16* __restrict__ Cs,
                 int N, int D, int F)
{
    __shared__ __align__(16) __nv_bfloat16 As[2][128 * 40];
    __shared__ __align__(16) __nv_bfloat16 Bs[2][128 * 40];
    __shared__ float benc_s[128];

    const int tid = threadIdx.x;
    const int m0 = blockIdx.y * 128, n0 = blockIdx.x * 128;
    if (tid < 128) benc_s[tid] = b_enc[n0 + tid];

    const int warp = tid >> 5, lane = tid & 31;
    const int wm = warp & 1, wn = warp >> 1;

    const int lrow = tid >> 2;           // 0..63
    const int lq   = (tid & 3) * 8;      // bf16 col: 0,8,16,24

    const __nv_bfloat16* Ag0 = A  + (size_t)(m0 + lrow) * D + lq;
    const __nv_bfloat16* Ag1 = A  + (size_t)(m0 + lrow + 64) * D + lq;
    const __nv_bfloat16* Bg0 = Bw + (size_t)(n0 + lrow) * D + lq;
    const __nv_bfloat16* Bg1 = Bw + (size_t)(n0 + lrow + 64) * D + lq;

    float acc[4][4][4];
    #pragma unroll
    for (int mi = 0; mi < 4; ++mi)
        #pragma unroll
        for (int ni = 0; ni < 4; ++ni)
            #pragma unroll
            for (int t = 0; t < 4; ++t) acc[mi][ni][t] = 0.f;

    const int arow_base = wm * 64 + (lane & 7) + ((lane & 8) ? 8 : 0);
    const int acol_base = (lane & 16) ? 8 : 0;
    const int brow_base = wn * 32 + (lane & 7) + ((lane & 16) ? 8 : 0);
    const int bcol_base = (lane & 8) ? 8 : 0;

    const int nt = D >> 5;   // K tiles of 32

    // pipeline prologue: stage 0
    {
        cp16(&As[0][lrow * 40 + lq],        Ag0);
        cp16(&As[0][(lrow + 64) * 40 + lq], Ag1);
        cp16(&Bs[0][lrow * 40 + lq],        Bg0);
        cp16(&Bs[0][(lrow + 64) * 40 + lq], Bg1);
        CP_COMMIT();
    }

    for (int t = 0; t < nt; ++t) {
        const bool more = (t + 1 < nt);
        if (more) {
            const int kk = (t + 1) << 5;
            const int nb = (t + 1) & 1;
            cp16(&As[nb][lrow * 40 + lq],        Ag0 + kk);
            cp16(&As[nb][(lrow + 64) * 40 + lq], Ag1 + kk);
            cp16(&Bs[nb][lrow * 40 + lq],        Bg0 + kk);
            cp16(&Bs[nb][(lrow + 64) * 40 + lq], Bg1 + kk);
            CP_COMMIT();
            CP_WAIT(1);
        } else {
            CP_WAIT(0);
        }
        __syncthreads();

        const __nv_bfloat16* Ab = As[t & 1];
        const __nv_bfloat16* Bb = Bs[t & 1];

        #pragma unroll
        for (int ks = 0; ks < 2; ++ks) {
            uint32_t af[4][4];
            const int acol = ks * 16 + acol_base;
            #pragma unroll
            for (int mi = 0; mi < 4; ++mi)
                ldsm4(af[mi][0], af[mi][1], af[mi][2], af[mi][3],
                      Ab + (arow_base + mi * 16) * 40 + acol);

            uint32_t bfr[4][2];
            const int bcol = ks * 16 + bcol_base;
            #pragma unroll
            for (int nj = 0; nj < 2; ++nj) {
                uint32_t r0, r1, r2, r3;
                ldsm4(r0, r1, r2, r3, Bb + (brow_base + nj * 16) * 40 + bcol);
                bfr[nj * 2][0] = r0; bfr[nj * 2][1] = r1;
                bfr[nj * 2 + 1][0] = r2; bfr[nj * 2 + 1][1] = r3;
            }

            #pragma unroll
            for (int mi = 0; mi < 4; ++mi)
                #pragma unroll
                for (int ni = 0; ni < 4; ++ni)
                    mma16816(acc[mi][ni], af[mi][0], af[mi][1], af[mi][2], af[mi][3],
                             bfr[ni][0], bfr[ni][1]);
        }
        __syncthreads();   // buffer t&1 free for prefetch at iter t+1
    }

    // epilogue: + b_enc, convert bf16, store (4B stores, screen buffer aligned)
    #pragma unroll
    for (int mi = 0; mi < 4; ++mi) {
        const int gm = m0 + wm * 64 + mi * 16 + (lane >> 2);
        #pragma unroll
        for (int ni = 0; ni < 4; ++ni) {
            const int ln = wn * 32 + ni * 8 + (lane & 3) * 2;
            const float be0 = benc_s[ln], be1 = benc_s[ln + 1];
            __nv_bfloat162 h0 = __floats2bfloat162_rn(acc[mi][ni][0] + be0, acc[mi][ni][1] + be1);
            __nv_bfloat162 h1 = __floats2bfloat162_rn(acc[mi][ni][2] + be0, acc[mi][ni][3] + be1);
            *(__nv_bfloat162*)(Cs + (size_t)gm * F + n0 + ln)       = h0;
            *(__nv_bfloat162*)(Cs + (size_t)(gm + 8) * F + n0 + ln) = h1;
        }
    }
}

// =================================================================================
// K2: per-row candidate selection on bf16 screened scores.
// 2-level radix finds threshold T (key of ncand-th largest); emit is UNORDERED
// compaction (>T then ==T capped) — order/ties don't matter: rescore re-ranks
// exactly and tie members at T are far below the exact top-K boundary.
// Also zero-fills the acts row (vectorized).
// =================================================================================
__global__ void cand_topk(const __nv_bfloat16* __restrict__ S, const int* __restrict__ pK,
                          float* __restrict__ acts, int F)
{
    extern __shared__ unsigned char smem_raw[];
    unsigned short* keys = (unsigned short*)smem_raw;        // F keys
    unsigned* hist = (unsigned*)(keys + F);                  // 256
    int* misc = (int*)(hist + 256);                          // [0]=digit [1]=gt [2]=cnt [3]=eq

    const int row = blockIdx.x;
    const int tid = threadIdx.x;
    const int ncand = ncand_of(clampK(*pK));
    const size_t rowoff = (size_t)row * F;

    // load + branchless vectorized key transform (2 elems per uint32)
    const uint32_t* rp = (const uint32_t*)(S + rowoff);
    uint32_t* kp = (uint32_t*)keys;
    for (int i = tid; i < (F >> 1); i += TPB) {
        uint32_t v = rp[i];
        uint32_t s = (v >> 15) & 0x00010001u;
        kp[i] = v ^ (s * 0x7FFFu) ^ 0x80008000u;
    }

    // vectorized zero-fill of acts row (handles the odd-float global offset)
    {
        float* ar = acts + rowoff;
        size_t addr = (size_t)ar;
        int head = (int)(((16 - (addr & 15)) & 15) >> 2);   // floats to 16B boundary
        if (head > F) head = F;
        if (tid < head) ar[tid] = 0.0f;
        const int nv = (F - head) >> 2;                      // # float4
        float4 z = make_float4(0.f, 0.f, 0.f, 0.f);
        float4* av = (float4*)(ar + head);
        for (int j = tid; j < nv; j += TPB) av[j] = z;
        const int tail0 = head + (nv << 2);
        if (tid < F - tail0) ar[tail0 + tid] = 0.0f;
    }
    __syncthreads();

    // ---- 2-level radix select (descending) to find T ----
    unsigned prefix = 0;
    int need = ncand;
    for (int lvl = 0; lvl < 2; ++lvl) {
        const int shift = (1 - lvl) * 8;
        hist[tid] = 0;
        __syncthreads();
        for (int i = tid; i < F; i += TPB) {
            unsigned u = keys[i];
            bool match = (lvl == 0) || ((u >> 8) == prefix);
            if (match) atomicAdd(&hist[(u >> shift) & 255u], 1u);
        }
        __syncthreads();
        for (int off = 1; off < 256; off <<= 1) {
            unsigned v = hist[tid];
            if (tid + off < 256) v += hist[tid + off];
            __syncthreads();
            hist[tid] = v;
            __syncthreads();
        }
        unsigned ge = hist[tid];
        unsigned gt = (tid == 255) ? 0u : hist[tid + 1];
        if ((int)ge >= need && (int)gt < need) { misc[0] = tid; misc[1] = (int)gt; }
        __syncthreads();
        need -= misc[1];
        prefix = (prefix << 8) | (unsigned)misc[0];
        __syncthreads();
    }
    const unsigned T = prefix;

    // ---- unordered emit: strictly-greater first ----
    if (tid == 0) { misc[2] = 0; misc[3] = 0; }
    __syncthreads();
    for (int i = tid; i < F; i += TPB) {
        if (keys[i] > T) {
            int p = atomicAdd(&misc[2], 1);     // p < ncand <= NCAND_MAX guaranteed
            g_cand[(size_t)row * NCAND_MAX + p] = i;
        }
    }
    __syncthreads();
    const int gt_total = misc[2];
    const int eq_cap = NCAND_MAX - gt_total;    // room for ties (>= ncand - gt)
    for (int i = tid; i < F; i += TPB) {
        if (keys[i] == T) {
            int e = atomicAdd(&misc[3], 1);
            if (e < eq_cap)
                g_cand[(size_t)row * NCAND_MAX + gt_total + e] = i;
        }
    }
    __syncthreads();
    if (tid == 0) {
        int e = misc[3]; if (e > eq_cap) e = eq_cap;
        g_candn[row] = gt_total + e;
    }
}

// =================================================================================
// K3: exact fp32 rescore of candidates + exact top-K ranking (ties: lowest index)
//     scatters winners into acts, records (idx,val) for decoder.
// =================================================================================
__global__ __launch_bounds__(256)
void rescore(const float* __restrict__ x, const float* __restrict__ W,
             const float* __restrict__ b_enc, const float* __restrict__ b_dec,
             const int* __restrict__ pK, float* __restrict__ acts, int D, int F)
{
    __shared__ float4 xc[MAXD / 4];
    __shared__ float sc[NCAND_MAX];
    __shared__ int   ci[NCAND_MAX];

    const int row = blockIdx.x;
    const int tid = threadIdx.x;
    const int K = clampK(*pK);
    const int tot = g_candn[row];
    const int D4 = D >> 2;

    for (int i = tid; i < D4; i += TPB) {
        float4 xv = ((const float4*)(x + (size_t)row * D))[i];
        float4 bv = ((const float4*)b_dec)[i];
        xc[i] = make_float4(xv.x - bv.x, xv.y - bv.y, xv.z - bv.z, xv.w - bv.w);
    }
    __syncthreads();

    const int warp = tid >> 5, lane = tid & 31;
    for (int c = warp; c < tot; c += 8) {
        const int f = g_cand[(size_t)row * NCAND_MAX + c];
        const float4* wr = (const float4*)(W + (size_t)f * D);
        float s = 0.f;
        for (int j = lane; j < D4; j += 32) {
            float4 w = wr[j]; float4 xv = xc[j];
            s = fmaf(xv.x, w.x, s); s = fmaf(xv.y, w.y, s);
            s = fmaf(xv.z, w.z, s); s = fmaf(xv.w, w.w, s);
        }
        #pragma unroll
        for (int off = 16; off > 0; off >>= 1)
            s += __shfl_down_sync(0xffffffffu, s, off);
        if (lane == 0) { sc[c] = s + b_enc[f]; ci[c] = f; }
    }
    __syncthreads();

    // exact ranking: rank = #{j beats i}; beats = (>) or (== && lower idx)
    for (int c = tid; c < tot; c += TPB) {
        const unsigned ki = fkey(sc[c]);
        const int idi = ci[c];
        int rank = 0;
        for (int j = 0; j < tot; ++j) {
            unsigned kj = fkey(sc[j]);
            rank += (kj > ki) || (kj == ki && ci[j] < idi);
        }
        if (rank < K) {
            g_win_idx[(row << 6) + rank] = idi;
            g_win_val[(row << 6) + rank] = sc[c];
            acts[(size_t)row * F + idi] = sc[c];
        }
    }
}

// =================================================================================
// K4: sparse decoder + per-row squared error (blockDim = D/4, float4 gathers)
// =================================================================================
__global__ void decoder_kernel(const float* __restrict__ x, const float* __restrict__ Wd,
                               const float* __restrict__ b_dec, const int* __restrict__ pK,
                               float* __restrict__ recon, int D)
{
    __shared__ int   wi[64];
    __shared__ float wv[64];
    __shared__ float red[MAXD / 4];
    const int row = blockIdx.x, tid = threadIdx.x;
    const int K = clampK(*pK);
    const int nthr = blockDim.x;                 // = D/4
    if (tid < K) { wi[tid] = g_win_idx[(row << 6) + tid]; wv[tid] = g_win_val[(row << 6) + tid]; }
    __syncthreads();

    float4 acc = ((const float4*)b_dec)[tid];
    #pragma unroll 4
    for (int j = 0; j < K; ++j) {
        float4 w = ((const float4*)(Wd + (size_t)wi[j] * D))[tid];
        const float v = wv[j];
        acc.x = fmaf(v, w.x, acc.x); acc.y = fmaf(v, w.y, acc.y);
        acc.z = fmaf(v, w.z, acc.z); acc.w = fmaf(v, w.w, acc.w);
    }
    float4 xv = ((const float4*)(x + (size_t)row * D))[tid];
    float* rr = recon + (size_t)row * D + tid * 4;    // recon base misaligned: scalar stores
    rr[0] = acc.x; rr[1] = acc.y; rr[2] = acc.z; rr[3] = acc.w;
    float dx = acc.x - xv.x, dy = acc.y - xv.y, dz = acc.z - xv.z, dw = acc.w - xv.w;
    float sq = dx * dx + dy * dy + dz * dz + dw * dw;

    red[tid] = sq;
    __syncthreads();
    for (int s = nthr / 2; s > 0; s >>= 1) {
        if (tid < s) red[tid] += red[tid + s];
        __syncthreads();
    }
    if (tid == 0) g_row_sq[row] = red[0];
}

// =================================================================================
// K5: loss = mean(row_sq)
// =================================================================================
__global__ void loss_kernel(float* __restrict__ out, int N)
{
    __shared__ float red[TPB];
    const int tid = threadIdx.x;
    float s = 0.f;
    for (int i = tid; i < N; i += TPB) s += g_row_sq[i];
    red[tid] = s;
    __syncthreads();
    for (int o = TPB / 2; o > 0; o >>= 1) {
        if (tid < o) red[tid] += red[tid + o];
        __syncthreads();
    }
    if (tid == 0) out[0] = red[0] / (float)N;
}

// =================================================================================
// launch: out = [loss(1), recon(N*D), acts(N*F)]
// =================================================================================
extern "C" void kernel_launch(void* const* d_in, const int* in_sizes, int n_in,
                              void* d_out, int out_size)
{
    const float* x   = (const float*)d_in[0];
    const float* W_e = (const float*)d_in[1];
    const float* W_d = (const float*)d_in[2];
    const float* b_e = (const float*)d_in[3];
    const float* b_d = (const float*)d_in[4];

    const int* pK;
    if (n_in >= 6) {
        pK = (const int*)d_in[5];
    } else {
        void* p = nullptr;
        cudaGetSymbolAddress(&p, g_defK);
        pK = (const int*)p;
    }

    const int D = in_sizes[4];
    const int F = in_sizes[3];
    const int N = in_sizes[0] / D;

    float* out   = (float*)d_out;
    float* recon = out + 1;
    float* acts  = out + 1 + (size_t)N * D;

    __nv_bfloat16 *Abf, *Wbf, *Scr;
    { void* p; cudaGetSymbolAddress(&p, g_Abf);    Abf = (__nv_bfloat16*)p; }
    { void* p; cudaGetSymbolAddress(&p, g_Wbf);    Wbf = (__nv_bfloat16*)p; }
    { void* p; cudaGetSymbolAddress(&p, g_screen); Scr = (__nv_bfloat16*)p; }

    // K0: bf16 conversions (vectorized)
    prep_x<<<512, 256>>>(x, b_d, Abf, N, D);
    prep_w<<<2048, 256>>>(W_e, Wbf, ((size_t)F * D) >> 2);

    // K1: bf16 tensor-core screening GEMM (mma.sync + cp.async pipeline)
    dim3 grid(F / 128, N / 128);
    gemm_screen<<<grid, TPB>>>(Abf, Wbf, b_e, Scr, N, D, F);

    // K2: candidate selection (+ zero acts rows)
    size_t smem2 = (size_t)F * 2 + 256 * 4 + 64 * 4;
    cand_topk<<<N, TPB, smem2>>>(Scr, pK, acts, F);

    // K3: exact rescore + exact top-K + scatter
    rescore<<<N, TPB>>>(x, W_e, b_e, b_d, pK, acts, D, F);

    // K4: sparse decoder + row squared error
    decoder_kernel<<<N, D / 4>>>(x, W_d, b_d, pK, recon, D);

    // K5: loss
    loss_kernel<<<1, TPB>>>(out, N);
}